// round 5
// baseline (speedup 1.0000x reference)
#include <cuda_runtime.h>
#include <cuda_fp16.h>
#include <cstdint>

// BMM_S8T_S8N_F16T warp-specialized hybrid:
//   warps 0-3: legacy IMMA tensor pipe, rows 0..63 of the CTA tile
//   warps 4-7: dp4a on ALU/FMA pipes,   rows 64..127
// out[b,m,n] = f32( fp16_round( alpha * sum_k a[b,m,k]*b[b,n,k] ) )

#define BATCH 64
#define MDIM 1024
#define NDIM 1024
#define KDIM 128

#define BM 128
#define BN 128
#define ROWSTRIDE 36       // 32 k-words + 4 pad words -> conflict-free banks

__global__ __launch_bounds__(256, 2)
void bmm_s8_ws_kernel(const int* __restrict__ A,
                      const int* __restrict__ Bmat,
                      const float* __restrict__ alpha_p,
                      float* __restrict__ Out) {
    __shared__ uint32_t As[BM * ROWSTRIDE];
    __shared__ uint32_t Bs[BN * ROWSTRIDE];

    const int tid  = threadIdx.x;
    const int lane = tid & 31;
    const int wid  = tid >> 5;

    const int bn = blockIdx.x;   // N block (8)
    const int bm = blockIdx.y;   // M block (8)
    const int bz = blockIdx.z;   // batch (64)

    const int* Abase = A    + ((size_t)bz * MDIM + (size_t)bm * BM) * KDIM;
    const int* Bbase = Bmat + ((size_t)bz * NDIM + (size_t)bn * BN) * KDIM;

    // ---- Load int32 tiles, pack to s8x4, stage in smem (all 8 warps) ----
    #pragma unroll
    for (int i = 0; i < 16; i++) {
        int idx = tid + i * 256;
        int row = idx >> 5;          // 0..127
        int col = idx & 31;          // word 0..31
        int4 va = *(const int4*)(Abase + row * KDIM + col * 4);
        uint32_t pa = (uint32_t)(va.x & 0xFF)
                    | ((uint32_t)(va.y & 0xFF) << 8)
                    | ((uint32_t)(va.z & 0xFF) << 16)
                    | ((uint32_t)(va.w & 0xFF) << 24);
        As[row * ROWSTRIDE + col] = pa;

        int4 vb = *(const int4*)(Bbase + row * KDIM + col * 4);
        uint32_t pb = (uint32_t)(vb.x & 0xFF)
                    | ((uint32_t)(vb.y & 0xFF) << 8)
                    | ((uint32_t)(vb.z & 0xFF) << 16)
                    | ((uint32_t)(vb.w & 0xFF) << 24);
        Bs[row * ROWSTRIDE + col] = pb;
    }
    __syncthreads();

    const float alpha = *alpha_p;
    float* obase = Out + ((size_t)bz * MDIM + (size_t)bm * BM) * NDIM + (size_t)bn * BN;

    if (wid < 4) {
        // ================= IMMA warps: rows 0..63 =================
        // warp tile 32(M) x 64(N): warp_m = wid>>1, warp_n = wid&1
        const int warp_m = wid >> 1;
        const int warp_n = wid & 1;
        const int lq = lane >> 2;   // 0..7
        const int lr = lane & 3;    // 0..3

        int acc[2][8][4];
        #pragma unroll
        for (int mi = 0; mi < 2; mi++)
            #pragma unroll
            for (int ni = 0; ni < 8; ni++)
                #pragma unroll
                for (int r = 0; r < 4; r++)
                    acc[mi][ni][r] = 0;

        #pragma unroll
        for (int ks = 0; ks < 4; ks++) {
            uint32_t af[2][4];
            #pragma unroll
            for (int mi = 0; mi < 2; mi++) {
                int r = warp_m * 32 + mi * 16 + lq;
                const uint32_t* p  = &As[r * ROWSTRIDE + ks * 8 + lr];
                af[mi][0] = p[0];
                af[mi][2] = p[4];
                const uint32_t* p8 = p + 8 * ROWSTRIDE;
                af[mi][1] = p8[0];
                af[mi][3] = p8[4];
            }
            uint32_t bf[8][2];
            #pragma unroll
            for (int ni = 0; ni < 8; ni++) {
                int c = warp_n * 64 + ni * 8 + lq;
                const uint32_t* p = &Bs[c * ROWSTRIDE + ks * 8 + lr];
                bf[ni][0] = p[0];
                bf[ni][1] = p[4];
            }
            #pragma unroll
            for (int mi = 0; mi < 2; mi++) {
                #pragma unroll
                for (int ni = 0; ni < 8; ni++) {
                    asm volatile(
                        "mma.sync.aligned.m16n8k32.row.col.s32.s8.s8.s32 "
                        "{%0,%1,%2,%3}, {%4,%5,%6,%7}, {%8,%9}, {%0,%1,%2,%3};"
                        : "+r"(acc[mi][ni][0]), "+r"(acc[mi][ni][1]),
                          "+r"(acc[mi][ni][2]), "+r"(acc[mi][ni][3])
                        : "r"(af[mi][0]), "r"(af[mi][1]), "r"(af[mi][2]), "r"(af[mi][3]),
                          "r"(bf[ni][0]), "r"(bf[ni][1]));
                }
            }
        }

        #pragma unroll
        for (int mi = 0; mi < 2; mi++) {
            #pragma unroll
            for (int ni = 0; ni < 8; ni++) {
                int r0 = warp_m * 32 + mi * 16 + lq;
                int c0 = warp_n * 64 + ni * 8 + lr * 2;
                float2 v0;
                v0.x = __half2float(__float2half_rn(alpha * (float)acc[mi][ni][0]));
                v0.y = __half2float(__float2half_rn(alpha * (float)acc[mi][ni][1]));
                *(float2*)(obase + (size_t)r0 * NDIM + c0) = v0;
                float2 v1;
                v1.x = __half2float(__float2half_rn(alpha * (float)acc[mi][ni][2]));
                v1.y = __half2float(__float2half_rn(alpha * (float)acc[mi][ni][3]));
                *(float2*)(obase + (size_t)(r0 + 8) * NDIM + c0) = v1;
            }
        }
    } else {
        // ================= dp4a warps: rows 64..127 =================
        // warp w covers 16 rows: 64 + w*16 .. +15, all 128 cols.
        // lane g = lane>>3 (row interleave), j = lane&7 (col interleave)
        // thread tile: rows rb + g + 4*mi (mi 0..3), cols j + 8*ni (ni 0..15)
        const int w  = wid - 4;
        const int rb = 64 + w * 16;
        const int g  = lane >> 3;
        const int j  = lane & 7;

        int acc[4][16];
        #pragma unroll
        for (int mi = 0; mi < 4; mi++)
            #pragma unroll
            for (int ni = 0; ni < 16; ni++)
                acc[mi][ni] = 0;

        #pragma unroll
        for (int chunk = 0; chunk < 8; chunk++) {
            const int kw = chunk * 4;
            uint4 av[4];
            #pragma unroll
            for (int mi = 0; mi < 4; mi++)
                av[mi] = *(const uint4*)&As[(rb + g + 4 * mi) * ROWSTRIDE + kw];

            #pragma unroll
            for (int ni = 0; ni < 16; ni++) {
                uint4 bv = *(const uint4*)&Bs[(j + 8 * ni) * ROWSTRIDE + kw];
                #pragma unroll
                for (int mi = 0; mi < 4; mi++) {
                    int v = acc[mi][ni];
                    v = __dp4a((int)av[mi].x, (int)bv.x, v);
                    v = __dp4a((int)av[mi].y, (int)bv.y, v);
                    v = __dp4a((int)av[mi].z, (int)bv.z, v);
                    v = __dp4a((int)av[mi].w, (int)bv.w, v);
                    acc[mi][ni] = v;
                }
            }
        }

        #pragma unroll
        for (int mi = 0; mi < 4; mi++) {
            const int row = rb + g + 4 * mi;
            float* orow = obase + (size_t)row * NDIM;
            #pragma unroll
            for (int ni = 0; ni < 16; ni++) {
                int col = j + 8 * ni;
                orow[col] = __half2float(__float2half_rn(alpha * (float)acc[mi][ni]));
            }
        }
    }
}

extern "C" void kernel_launch(void* const* d_in, const int* in_sizes, int n_in,
                              void* d_out, int out_size) {
    // alpha is the size-1 input; the two large tensors are a then b in index order.
    int ai = -1, bi = -1, si = -1;
    for (int i = 0; i < n_in; i++) {
        if (in_sizes[i] == 1) { si = i; }
        else if (ai < 0)      { ai = i; }
        else                  { bi = i; }
    }
    const int*   a     = (const int*)d_in[ai];
    const int*   b     = (const int*)d_in[bi];
    const float* alpha = (const float*)d_in[si];
    float*       out   = (float*)d_out;

    dim3 grid(NDIM / BN, MDIM / BM, BATCH);   // (8, 8, 64)
    dim3 block(256);
    bmm_s8_ws_kernel<<<grid, block>>>(a, b, alpha, out);
}

// round 6
// speedup vs baseline: 1.0363x; 1.0363x over previous
#include <cuda_runtime.h>
#include <cuda_fp16.h>
#include <cstdint>

// BMM_S8T_S8N_F16T homogeneous-warp hybrid:
// each warp owns a 16-row slab; IMMA covers cols 0..71, dp4a covers cols 72..127,
// independent accumulators, interleaved per k-step so both pipes run concurrently.
// out[b,m,n] = f32( fp16_round( alpha * sum_k a[b,m,k]*b[b,n,k] ) )

#define BATCH 64
#define MDIM 1024
#define NDIM 1024
#define KDIM 128

#define BM 128
#define BN 128
#define ROWSTRIDE 36       // 32 k-words + 4 pad words -> conflict-free banks

#define NI_MMA 9           // IMMA cols: 9*8 = 72
#define COL_DP 72          // dp4a cols 72..127
#define NI_DP 7            // 7*8 = 56 cols

__global__ __launch_bounds__(256, 2)
void bmm_s8_mix_kernel(const int* __restrict__ A,
                       const int* __restrict__ Bmat,
                       const float* __restrict__ alpha_p,
                       float* __restrict__ Out) {
    __shared__ uint32_t As[BM * ROWSTRIDE];
    __shared__ uint32_t Bs[BN * ROWSTRIDE];

    const int tid  = threadIdx.x;
    const int lane = tid & 31;
    const int wid  = tid >> 5;

    const int bn = blockIdx.x;
    const int bm = blockIdx.y;
    const int bz = blockIdx.z;

    const int* Abase = A    + ((size_t)bz * MDIM + (size_t)bm * BM) * KDIM;
    const int* Bbase = Bmat + ((size_t)bz * NDIM + (size_t)bn * BN) * KDIM;

    // ---- Load int32 tiles, pack to s8x4 (byte_perm), stage in smem ----
    #pragma unroll
    for (int i = 0; i < 16; i++) {
        int idx = tid + i * 256;
        int row = idx >> 5;
        int col = idx & 31;
        int4 va = *(const int4*)(Abase + row * KDIM + col * 4);
        uint32_t pa = __byte_perm(__byte_perm(va.x, va.y, 0x0040),
                                  __byte_perm(va.z, va.w, 0x0040), 0x5410);
        As[row * ROWSTRIDE + col] = pa;

        int4 vb = *(const int4*)(Bbase + row * KDIM + col * 4);
        uint32_t pb = __byte_perm(__byte_perm(vb.x, vb.y, 0x0040),
                                  __byte_perm(vb.z, vb.w, 0x0040), 0x5410);
        Bs[row * ROWSTRIDE + col] = pb;
    }
    __syncthreads();

    // ---- Warp slab: rows wid*16 .. wid*16+15 ----
    const int rb = wid * 16;
    const int lq = lane >> 2;    // mma group id 0..7
    const int lr = lane & 3;     // mma thread-in-group 0..3
    const int g  = lane >> 3;    // dp4a row interleave 0..3
    const int j  = lane & 7;     // dp4a col interleave 0..7

    int macc[NI_MMA][4];
    #pragma unroll
    for (int ni = 0; ni < NI_MMA; ni++)
        #pragma unroll
        for (int r = 0; r < 4; r++)
            macc[ni][r] = 0;

    int dacc[4][NI_DP];
    #pragma unroll
    for (int mi = 0; mi < 4; mi++)
        #pragma unroll
        for (int ni = 0; ni < NI_DP; ni++)
            dacc[mi][ni] = 0;

    #pragma unroll
    for (int ks = 0; ks < 4; ks++) {
        // --- IMMA: rows rb..rb+15, cols 0..71, k = ks*32..+31 ---
        uint32_t af[4];
        {
            const uint32_t* p  = &As[(rb + lq) * ROWSTRIDE + ks * 8 + lr];
            af[0] = p[0];
            af[2] = p[4];
            const uint32_t* p8 = p + 8 * ROWSTRIDE;
            af[1] = p8[0];
            af[3] = p8[4];
        }
        #pragma unroll
        for (int ni = 0; ni < NI_MMA; ni++) {
            const uint32_t* p = &Bs[(ni * 8 + lq) * ROWSTRIDE + ks * 8 + lr];
            uint32_t b0 = p[0];
            uint32_t b1 = p[4];
            asm volatile(
                "mma.sync.aligned.m16n8k32.row.col.s32.s8.s8.s32 "
                "{%0,%1,%2,%3}, {%4,%5,%6,%7}, {%8,%9}, {%0,%1,%2,%3};"
                : "+r"(macc[ni][0]), "+r"(macc[ni][1]),
                  "+r"(macc[ni][2]), "+r"(macc[ni][3])
                : "r"(af[0]), "r"(af[1]), "r"(af[2]), "r"(af[3]),
                  "r"(b0), "r"(b1));
        }

        // --- dp4a: rows rb..rb+15, cols 72..127, same k range (8 k-words) ---
        #pragma unroll
        for (int c = 0; c < 2; c++) {
            const int kw = ks * 8 + c * 4;
            uint4 av[4];
            #pragma unroll
            for (int mi = 0; mi < 4; mi++)
                av[mi] = *(const uint4*)&As[(rb + g + 4 * mi) * ROWSTRIDE + kw];
            #pragma unroll
            for (int ni = 0; ni < NI_DP; ni++) {
                uint4 bv = *(const uint4*)&Bs[(COL_DP + j + 8 * ni) * ROWSTRIDE + kw];
                #pragma unroll
                for (int mi = 0; mi < 4; mi++) {
                    int v = dacc[mi][ni];
                    v = __dp4a((int)av[mi].x, (int)bv.x, v);
                    v = __dp4a((int)av[mi].y, (int)bv.y, v);
                    v = __dp4a((int)av[mi].z, (int)bv.z, v);
                    v = __dp4a((int)av[mi].w, (int)bv.w, v);
                    dacc[mi][ni] = v;
                }
            }
        }
    }

    // ---- Epilogue ----
    const float alpha = *alpha_p;
    float* obase = Out + ((size_t)bz * MDIM + (size_t)bm * BM) * NDIM + (size_t)bn * BN;

    // IMMA outputs: rows rb+lq (+8), cols ni*8 + lr*2 (+1)
    #pragma unroll
    for (int ni = 0; ni < NI_MMA; ni++) {
        int c0 = ni * 8 + lr * 2;
        float2 v0;
        v0.x = __half2float(__float2half_rn(alpha * (float)macc[ni][0]));
        v0.y = __half2float(__float2half_rn(alpha * (float)macc[ni][1]));
        *(float2*)(obase + (size_t)(rb + lq) * NDIM + c0) = v0;
        float2 v1;
        v1.x = __half2float(__float2half_rn(alpha * (float)macc[ni][2]));
        v1.y = __half2float(__float2half_rn(alpha * (float)macc[ni][3]));
        *(float2*)(obase + (size_t)(rb + lq + 8) * NDIM + c0) = v1;
    }

    // dp4a outputs: rows rb + g + 4*mi, cols COL_DP + j + 8*ni
    #pragma unroll
    for (int mi = 0; mi < 4; mi++) {
        float* orow = obase + (size_t)(rb + g + 4 * mi) * NDIM;
        #pragma unroll
        for (int ni = 0; ni < NI_DP; ni++) {
            int col = COL_DP + j + 8 * ni;
            orow[col] = __half2float(__float2half_rn(alpha * (float)dacc[mi][ni]));
        }
    }
}

extern "C" void kernel_launch(void* const* d_in, const int* in_sizes, int n_in,
                              void* d_out, int out_size) {
    // alpha is the size-1 input; the two large tensors are a then b in index order.
    int ai = -1, bi = -1, si = -1;
    for (int i = 0; i < n_in; i++) {
        if (in_sizes[i] == 1) { si = i; }
        else if (ai < 0)      { ai = i; }
        else                  { bi = i; }
    }
    const int*   a     = (const int*)d_in[ai];
    const int*   b     = (const int*)d_in[bi];
    const float* alpha = (const float*)d_in[si];
    float*       out   = (float*)d_out;

    dim3 grid(NDIM / BN, MDIM / BM, BATCH);   // (8, 8, 64)
    dim3 block(256);
    bmm_s8_mix_kernel<<<grid, block>>>(a, b, alpha, out);
}